// round 2
// baseline (speedup 1.0000x reference)
#include <cuda_runtime.h>
#include <cstdint>
#include <cstdio>

// ---------------------------------------------------------------------------
// HierarchicalAttention: two independent block-diagonal MHAs.
//   local : lqs [2,4096,1024], window 256  -> 32 windows x 16 heads
//   global: gqs [2,4096,1024], window 1024 ->  8 windows x 16 heads
// Output: concat(local_out, global_out), each [2,4096,1024] f32.
// ---------------------------------------------------------------------------

#define D_MODEL   1024
#define D3        3072
#define N_HEADS   16
#define HD        64
#define M_ROWS    8192           // B*S = 2*4096

// Scratch (allocation-free: __device__ globals)
__device__ float g_qkv[(size_t)M_ROWS * D3];            // 100.7 MB
__device__ float g_scores[134217728ULL];                // 536.9 MB (worst case: 128 pairs * 1024 * 1024)
__device__ float g_attn[(size_t)M_ROWS * D_MODEL];      // 33.6 MB

// ---------------------------------------------------------------------------
// Generic tiled SGEMM:  C[M,N] = A[M,K] @ B[N,K]^T + bias[N]
// 64x64 tile, BK=16, 128 threads, each thread computes 8(m) x 4(n).
// Requires M%64==0, N%64==0, K%16==0 (true for all our shapes).
// ---------------------------------------------------------------------------
__global__ __launch_bounds__(128) void gemm_nt_bias(
    const float* __restrict__ A, const float* __restrict__ B,
    const float* __restrict__ bias, float* __restrict__ C,
    int M, int N, int K)
{
    __shared__ float As[64][17];
    __shared__ float Bs[64][17];
    const int t  = threadIdx.x;
    const int tx = t & 15, ty = t >> 4;
    const int m0 = blockIdx.y * 64, n0 = blockIdx.x * 64;

    float acc[8][4] = {};

    for (int k0 = 0; k0 < K; k0 += 16) {
        #pragma unroll
        for (int r = 0; r < 2; r++) {
            int li  = t + r * 128;
            int row = li >> 2, q = li & 3;
            float4 va = *reinterpret_cast<const float4*>(&A[(size_t)(m0 + row) * K + k0 + q * 4]);
            As[row][q*4+0] = va.x; As[row][q*4+1] = va.y;
            As[row][q*4+2] = va.z; As[row][q*4+3] = va.w;
            float4 vb = *reinterpret_cast<const float4*>(&B[(size_t)(n0 + row) * K + k0 + q * 4]);
            Bs[row][q*4+0] = vb.x; Bs[row][q*4+1] = vb.y;
            Bs[row][q*4+2] = vb.z; Bs[row][q*4+3] = vb.w;
        }
        __syncthreads();
        #pragma unroll
        for (int kk = 0; kk < 16; kk++) {
            float a[8], b[4];
            #pragma unroll
            for (int u = 0; u < 8; u++) a[u] = As[ty*8 + u][kk];
            #pragma unroll
            for (int v = 0; v < 4; v++) b[v] = Bs[tx*4 + v][kk];
            #pragma unroll
            for (int u = 0; u < 8; u++)
                #pragma unroll
                for (int v = 0; v < 4; v++)
                    acc[u][v] += a[u] * b[v];
        }
        __syncthreads();
    }

    #pragma unroll
    for (int u = 0; u < 8; u++) {
        int m = m0 + ty*8 + u;
        #pragma unroll
        for (int v = 0; v < 4; v++) {
            int n = n0 + tx*4 + v;
            C[(size_t)m * N + n] = acc[u][v] + bias[n];
        }
    }
}

// ---------------------------------------------------------------------------
// Attention scores (batched):  S[p, i, j] = scale * dot(Q_i, K_j), depth 64.
// grid: (W/64 j-tiles, W/64 i-tiles, pairs). pair p: bw = p>>4, h = p&15.
// Q rows live at g_qkv[(bw*W + i)*3072 + h*64 + d], K at +1024.
// ---------------------------------------------------------------------------
__global__ __launch_bounds__(128) void attn_scores(float* __restrict__ S, int W, float scale)
{
    const int p  = blockIdx.z;
    const int bw = p >> 4, h = p & 15;
    const float* Qb = g_qkv + (size_t)bw * W * D3 + h * HD;
    const float* Kb = Qb + D_MODEL;

    __shared__ float Qs[64][65];
    __shared__ float Ks[64][65];

    const int t  = threadIdx.x;
    const int tx = t & 15, ty = t >> 4;
    const int i0 = blockIdx.y * 64, j0 = blockIdx.x * 64;

    #pragma unroll
    for (int r = 0; r < 8; r++) {
        int li  = t + r * 128;
        int row = li >> 4, q = li & 15;
        float4 vq = *reinterpret_cast<const float4*>(&Qb[(size_t)(i0 + row) * D3 + q * 4]);
        Qs[row][q*4+0] = vq.x; Qs[row][q*4+1] = vq.y;
        Qs[row][q*4+2] = vq.z; Qs[row][q*4+3] = vq.w;
        float4 vk = *reinterpret_cast<const float4*>(&Kb[(size_t)(j0 + row) * D3 + q * 4]);
        Ks[row][q*4+0] = vk.x; Ks[row][q*4+1] = vk.y;
        Ks[row][q*4+2] = vk.z; Ks[row][q*4+3] = vk.w;
    }
    __syncthreads();

    float acc[8][4] = {};
    #pragma unroll
    for (int d = 0; d < 64; d++) {
        float a[8], b[4];
        #pragma unroll
        for (int u = 0; u < 8; u++) a[u] = Qs[ty*8 + u][d];
        #pragma unroll
        for (int v = 0; v < 4; v++) b[v] = Ks[tx*4 + v][d];
        #pragma unroll
        for (int u = 0; u < 8; u++)
            #pragma unroll
            for (int v = 0; v < 4; v++)
                acc[u][v] += a[u] * b[v];
    }

    float* Sp = S + (size_t)p * W * W;
    #pragma unroll
    for (int u = 0; u < 8; u++)
        #pragma unroll
        for (int v = 0; v < 4; v++)
            Sp[(size_t)(i0 + ty*8 + u) * W + (j0 + tx*4 + v)] = acc[u][v] * scale;
}

// ---------------------------------------------------------------------------
// Row softmax over rows of length W (256 or 1024). One 256-thread CTA per row.
// ---------------------------------------------------------------------------
__global__ __launch_bounds__(256) void softmax_rows(float* __restrict__ S, int W)
{
    float* p = S + (size_t)blockIdx.x * W;
    const int t = threadIdx.x;
    __shared__ float red[256];

    float m = -1e30f;
    for (int j = t; j < W; j += 256) m = fmaxf(m, p[j]);
    red[t] = m; __syncthreads();
    #pragma unroll
    for (int s = 128; s > 0; s >>= 1) {
        if (t < s) red[t] = fmaxf(red[t], red[t + s]);
        __syncthreads();
    }
    m = red[0];
    __syncthreads();

    float e[4];
    float sum = 0.f;
    int k = 0;
    for (int j = t; j < W; j += 256) {
        float v = expf(p[j] - m);
        e[k++] = v;
        sum += v;
    }
    red[t] = sum; __syncthreads();
    #pragma unroll
    for (int s = 128; s > 0; s >>= 1) {
        if (t < s) red[t] += red[t + s];
        __syncthreads();
    }
    float inv = 1.f / red[0];

    k = 0;
    for (int j = t; j < W; j += 256) p[j] = e[k++] * inv;
}

// ---------------------------------------------------------------------------
// attn_out (batched): O[p, i, d] = sum_j P[p,i,j] * V[j,d]  (d = 0..63)
// grid: (1, W/64 i-tiles, pairs). Writes g_attn[(bw*W+i)*1024 + h*64 + d].
// ---------------------------------------------------------------------------
__global__ __launch_bounds__(128) void attn_out(const float* __restrict__ S, int W)
{
    const int p  = blockIdx.z;
    const int bw = p >> 4, h = p & 15;
    const float* Sp = S + (size_t)p * W * W;
    const float* Vb = g_qkv + (size_t)bw * W * D3 + 2 * D_MODEL + h * HD;
    float* Ob = g_attn + (size_t)bw * W * D_MODEL + h * HD;

    __shared__ float Ps[64][17];
    __shared__ float Vs[16][65];

    const int t  = threadIdx.x;
    const int tx = t & 15, ty = t >> 4;
    const int i0 = blockIdx.y * 64;

    float acc[8][4] = {};

    for (int k0 = 0; k0 < W; k0 += 16) {
        #pragma unroll
        for (int r = 0; r < 2; r++) {
            int li  = t + r * 128;
            int row = li >> 2, q = li & 3;
            float4 vp = *reinterpret_cast<const float4*>(&Sp[(size_t)(i0 + row) * W + k0 + q * 4]);
            Ps[row][q*4+0] = vp.x; Ps[row][q*4+1] = vp.y;
            Ps[row][q*4+2] = vp.z; Ps[row][q*4+3] = vp.w;
        }
        #pragma unroll
        for (int r = 0; r < 2; r++) {
            int li  = t + r * 128;
            int row = li >> 4, q = li & 15;   // row 0..15, q 0..15
            float4 vv = *reinterpret_cast<const float4*>(&Vb[(size_t)(k0 + row) * D3 + q * 4]);
            Vs[row][q*4+0] = vv.x; Vs[row][q*4+1] = vv.y;
            Vs[row][q*4+2] = vv.z; Vs[row][q*4+3] = vv.w;
        }
        __syncthreads();
        #pragma unroll
        for (int kk = 0; kk < 16; kk++) {
            float a[8], b[4];
            #pragma unroll
            for (int u = 0; u < 8; u++) a[u] = Ps[ty*8 + u][kk];
            #pragma unroll
            for (int v = 0; v < 4; v++) b[v] = Vs[kk][tx*4 + v];
            #pragma unroll
            for (int u = 0; u < 8; u++)
                #pragma unroll
                for (int v = 0; v < 4; v++)
                    acc[u][v] += a[u] * b[v];
        }
        __syncthreads();
    }

    #pragma unroll
    for (int u = 0; u < 8; u++)
        #pragma unroll
        for (int v = 0; v < 4; v++)
            Ob[(size_t)(i0 + ty*8 + u) * D_MODEL + tx*4 + v] = acc[u][v];
}

// ---------------------------------------------------------------------------
// Launch sequence (graph-capturable: kernel launches only)
// ---------------------------------------------------------------------------
static void run_branch(const float* x, const float* w_in, const float* b_in,
                       const float* w_out, const float* b_out,
                       float* out, int W,
                       float* qkv_ptr, float* scores_ptr, float* attn_ptr)
{
    const int pairs = (M_ROWS / W) * N_HEADS;     // (B*nw)*heads
    const float scale = 0.125f;                    // 1/sqrt(64)

    // 1) QKV projection: [8192,1024] @ [1024,3072(T)] -> g_qkv
    gemm_nt_bias<<<dim3(D3 / 64, M_ROWS / 64), 128>>>(x, w_in, b_in, qkv_ptr,
                                                      M_ROWS, D3, D_MODEL);
    // 2) scores
    attn_scores<<<dim3(W / 64, W / 64, pairs), 128>>>(scores_ptr, W, scale);
    // 3) softmax: pairs * W rows
    softmax_rows<<<(unsigned)((size_t)pairs * W), 256>>>(scores_ptr, W);
    // 4) P @ V -> g_attn
    attn_out<<<dim3(1, W / 64, pairs), 128>>>(scores_ptr, W);
    // 5) out projection: [8192,1024] @ [1024,1024(T)] -> out
    gemm_nt_bias<<<dim3(D_MODEL / 64, M_ROWS / 64), 128>>>(attn_ptr, w_out, b_out, out,
                                                           M_ROWS, D_MODEL, D_MODEL);
}

extern "C" void kernel_launch(void* const* d_in, const int* in_sizes, int n_in,
                              void* d_out, int out_size)
{
    const float* lqs   = (const float*)d_in[0];
    const float* gqs   = (const float*)d_in[1];
    const float* w_l   = (const float*)d_in[2];
    const float* b_l   = (const float*)d_in[3];
    const float* wo_l  = (const float*)d_in[4];
    const float* bo_l  = (const float*)d_in[5];
    const float* w_g   = (const float*)d_in[6];
    const float* b_g   = (const float*)d_in[7];
    const float* wo_g  = (const float*)d_in[8];
    const float* bo_g  = (const float*)d_in[9];

    float* out_l = (float*)d_out;
    float* out_g = out_l + (size_t)M_ROWS * D_MODEL;

    float *qkv_ptr = nullptr, *scores_ptr = nullptr, *attn_ptr = nullptr;
    cudaGetSymbolAddress((void**)&qkv_ptr,    g_qkv);
    cudaGetSymbolAddress((void**)&scores_ptr, g_scores);
    cudaGetSymbolAddress((void**)&attn_ptr,   g_attn);

    // local branch (window 256), then global branch (window 1024); scratch reused sequentially
    run_branch(lqs, w_l, b_l, wo_l, bo_l, out_l, 256,  qkv_ptr, scores_ptr, attn_ptr);
    run_branch(gqs, w_g, b_g, wo_g, bo_g, out_g, 1024, qkv_ptr, scores_ptr, attn_ptr);
}